// round 15
// baseline (speedup 1.0000x reference)
#include <cuda_runtime.h>
#include <cuda_fp16.h>
#include <math.h>
#include <stdint.h>

#define M_BATCH 2048
#define N_OUT   4096
#define K_IN    4096
#define NCTA    296
#define NITEMS  5120u          // 128 (Wgrp31) + 1024 (x) + 3968 (W desc)
#define EPSTRIDE 5416u         // NITEMS + NCTA (max overshoot)

// Persistent state (module-load allocations; no runtime alloc).
__device__ __half g_xh[(size_t)M_BATCH * K_IN];   // fp16(x)
__device__ __half g_wh[(size_t)N_OUT * K_IN];     // fp16(Wm)  (UNscaled)
__device__ float  g_coef[N_OUT];                  // exp(wls)/norm
__device__ unsigned g_entry;                      // epoch counter
__device__ unsigned g_qhead;                      // work-queue head (monotonic)
__device__ unsigned g_wcnt[32];                   // per-W-group completion
__device__ unsigned g_xcnt[16];                   // per-x-group completion

// ---------------------------------------------------------------------------
__device__ __forceinline__ uint32_t smem_u32(const void* p) {
    uint32_t a;
    asm("{ .reg .u64 t; cvta.to.shared.u64 t, %1; cvt.u32.u64 %0, t; }"
        : "=r"(a) : "l"(p));
    return a;
}
__device__ __forceinline__ void cp16(uint32_t s, const void* g) {
    asm volatile("cp.async.cg.shared.global [%0], [%1], 16;" :: "r"(s), "l"(g));
}
#define CP_COMMIT() asm volatile("cp.async.commit_group;" ::: "memory")
#define CP_WAIT0()  asm volatile("cp.async.wait_group 0;" ::: "memory")

#define LDM4(d, addr)                                                         \
    asm volatile("ldmatrix.sync.aligned.m8n8.x4.shared.b16 {%0,%1,%2,%3}, [%4];" \
        : "=r"((d)[0]), "=r"((d)[1]), "=r"((d)[2]), "=r"((d)[3]) : "r"(addr))

#define MMAF16(c, a, b0, b1)                                                  \
    asm volatile("mma.sync.aligned.m16n8k16.row.col.f32.f16.f16.f32 "         \
        "{%0,%1,%2,%3}, {%4,%5,%6,%7}, {%8,%9}, {%0,%1,%2,%3};"               \
        : "+f"((c)[0]), "+f"((c)[1]), "+f"((c)[2]), "+f"((c)[3])              \
        : "r"((a)[0]), "r"((a)[1]), "r"((a)[2]), "r"((a)[3]), "r"(b0), "r"(b1))

__device__ __forceinline__ uint32_t pack2(float a, float b) {
    __half2 h = __halves2half2(__float2half_rn(a), __float2half_rn(b));
    return *(uint32_t*)&h;
}

// ---------------------------------------------------------------------------
// Prep work items (CTA-collective, 128 threads).
//   idx <128        : W row 4095-idx              (group 31 first)
//   128<=idx<1152   : x item (2 rows), ascending  (groups 0..15)
//   idx>=1152       : W row 3967-(idx-1152)       (groups 30..0, descending)
// W item: single pass: read row, write fp16(Wm) (UNscaled), accumulate norm,
// store coef, write jac closed-form, zero-pad to tile K bound.
// ---------------------------------------------------------------------------
__device__ __noinline__ void do_item(unsigned idx,
                                     const float* __restrict__ W,
                                     const float* __restrict__ wls,
                                     const float* __restrict__ xin,
                                     float* __restrict__ jac,
                                     float* sred) {
    const int tid = threadIdx.x;
    if (idx < 128u || idx >= 1152u) {
        const int o = (idx < 128u) ? (4095 - (int)idx)
                                   : (3967 - (int)(idx - 1152u));
        const int br = o >> 5, ncols = (br + 1) << 5, dstart = br << 5;
        const int kmax = ((o >> 7) + 1) << 7;
        const float* wrow = W + (size_t)o * K_IN;
        __half* wh = g_wh + (size_t)o * K_IN;

        float ss = 0.f;
        for (int base = tid * 8; base < ncols; base += 1024) {
            float4 a = *(const float4*)(wrow + base);
            float4 b = *(const float4*)(wrow + base + 4);
            float w[8] = { a.x, a.y, a.z, a.w, b.x, b.y, b.z, b.w };
            float wn[8];
            #pragma unroll
            for (int e = 0; e < 8; e++) {
                float wm = (base + e >= dstart) ? expf(w[e]) : w[e];
                wn[e] = wm;
                ss += wm * wm;
            }
            uint4 out = { pack2(wn[0], wn[1]), pack2(wn[2], wn[3]),
                          pack2(wn[4], wn[5]), pack2(wn[6], wn[7]) };
            *(uint4*)(wh + base) = out;
        }
        const uint4 z4 = {0u, 0u, 0u, 0u};
        for (int base = ncols + tid * 8; base < kmax; base += 1024)
            *(uint4*)(wh + base) = z4;

        #pragma unroll
        for (int off = 16; off; off >>= 1)
            ss += __shfl_xor_sync(0xffffffffu, ss, off);
        if ((tid & 31) == 0) sred[tid >> 5] = ss;
        __syncthreads();
        if (tid == 0) {
            float s2 = sred[0] + sred[1] + sred[2] + sred[3];
            float norm = sqrtf(s2);
            float ls = wls[o];
            g_coef[o] = expf(ls) / norm;
            sred[4] = ls - logf(norm);
        }
        __syncthreads();
        if (tid < 32)
            jac[(size_t)o * 32 + tid] = sred[4] + wrow[dstart + tid];
        __threadfence();
        __syncthreads();
        if (tid == 0) atomicAdd(&g_wcnt[o >> 7], 1u);
    } else {
        const int k = (int)idx - 128;                 // x item: rows 2k, 2k+1
        const size_t base = (size_t)k * 8192;
        #pragma unroll
        for (int u = 0; u < 8; u++) {
            size_t i = base + (size_t)u * 1024 + tid * 8;
            float4 a = *(const float4*)(xin + i);
            float4 b = *(const float4*)(xin + i + 4);
            uint4 out = { pack2(a.x, a.y), pack2(a.z, a.w),
                          pack2(b.x, b.y), pack2(b.z, b.w) };
            *(uint4*)(&g_xh[i]) = out;
        }
        __threadfence();
        __syncthreads();
        if (tid == 0) atomicAdd(&g_xcnt[k >> 6], 1u);
    }
}

// Gate: until (W group gw, x group gx) complete for this epoch, pop and run
// prep items. Never blocks without either working or another CTA holding an
// in-flight item -> deadlock-free.
__device__ void gate_work(int gw, int gx, unsigned ep,
                          const float* W, const float* wls,
                          const float* xin, float* jac,
                          float* sred, unsigned* s_stat) {
    const int tid = threadIdx.x;
    const unsigned wt = (ep + 1u) * 128u;
    const unsigned xt = (ep + 1u) * 64u;
    const unsigned qbase = ep * EPSTRIDE;
    bool can_grab = true;                 // tid0-private
    while (true) {
        if (tid == 0) {
            if (atomicAdd(&g_wcnt[gw], 0u) >= wt &&
                atomicAdd(&g_xcnt[gx], 0u) >= xt) {
                *s_stat = 0xFFFFFFFFu;                     // ready
            } else if (can_grab) {
                unsigned p = atomicAdd(&g_qhead, 1u) - qbase;
                if (p < NITEMS) *s_stat = p;
                else { can_grab = false; *s_stat = 0xFFFFFFFEu; }
            } else {
                __nanosleep(200);
                *s_stat = 0xFFFFFFFEu;                     // spin
            }
        }
        __syncthreads();
        const unsigned st = *s_stat;
        __syncthreads();
        if (st == 0xFFFFFFFFu) break;
        if (st != 0xFFFFFFFEu) do_item(st, W, wls, xin, jac, sred);
    }
}

// ---------------------------------------------------------------------------
// Fused persistent kernel: work-stealing prep + gated fp16 GEMM.
// 296 CTAs (2/SM), 128 threads (2m x 2n warps => 64x64), CTA tile 128x128,
// BK=64, 3-stage cp.async, register-pipelined mainloop (R14).
// y = coef[o] * (fp16(x) @ fp16(Wm)^T) + bias   (coef applied in epilogue).
// Static flat schedule: slot s runs tile j=s, then j=591-s if 80<=s<=295.
// ---------------------------------------------------------------------------
#define STAGE 32768
#define NSTAGE 3
#define SMEM_TOTAL (NSTAGE * STAGE)

__device__ __forceinline__ uint32_t a_addr(uint32_t base, int wm, int lane,
                                           int mf, int ks) {
    const int row = (wm << 6) + (mf << 4) + (lane & 15);
    const int ch = ((ks << 1) + (lane >> 4)) ^ (row & 7);
    return base + (row << 7) + (ch << 4);
}
__device__ __forceinline__ uint32_t b_addr(uint32_t base, int wn, int lane,
                                           int ng, int ks) {
    const int n = (wn << 6) + (ng << 4) + ((lane >> 4) << 3) + (lane & 7);
    const int ch = ((ks << 1) + ((lane >> 3) & 1)) ^ (n & 7);
    return base + 16384 + (n << 7) + (ch << 4);
}

__global__ __launch_bounds__(128, 2)
void fused(const float* __restrict__ xin, const float* __restrict__ W,
           const float* __restrict__ wls, const float* __restrict__ bias,
           float* __restrict__ y, float* __restrict__ jac) {
    extern __shared__ __align__(1024) char smem[];
    const uint32_t sb = smem_u32(smem);
    float* sred = (float*)smem;                    // scratch (stages idle)
    unsigned* s_stat = (unsigned*)(smem + 64);

    const int tid  = threadIdx.x;
    const int wid  = tid >> 5;
    const int lane = tid & 31;
    const int wm = wid >> 1;
    const int wn = wid & 1;

    __shared__ unsigned s_ep;
    if (tid == 0) {
        unsigned v = atomicAdd(&g_entry, 1u);
        unsigned e = v / NCTA;
        atomicMax(&g_qhead, e * EPSTRIDE);         // fast-forward queue
        s_ep = e;
    }
    __syncthreads();
    const unsigned ep = s_ep;

    const int s = blockIdx.x;
    const int ntiles = (s >= 80) ? 2 : 1;

    int j = s;
    int nt = 31 - (j >> 4);
    int mt = j & 15;
    int n0 = nt << 7;
    int m0 = mt << 7;
    int NC = (nt + 1) << 1;

    const __half* gA = g_xh + (size_t)m0 * K_IN;
    const __half* gB = g_wh + (size_t)n0 * K_IN;

    auto load_stage = [&](int st, int c) {
        const uint32_t base = sb + st * STAGE;
        const int k0 = c << 6;
        #pragma unroll
        for (int i = 0; i < 8; i++) {
            const int idx = tid + (i << 7);
            const int r = idx >> 3;
            const int ch = idx & 7;
            const size_t go = (size_t)r * K_IN + k0 + (ch << 3);
            const uint32_t so = (uint32_t)((r << 7) | ((ch ^ (r & 7)) << 4));
            cp16(base + so,         gA + go);
            cp16(base + 16384 + so, gB + go);
        }
    };

    // Gate tile 0 (works the prep queue while waiting), then prologue.
    gate_work(nt, mt, ep, W, wls, xin, jac, sred, s_stat);
    __threadfence();
    __syncthreads();
    load_stage(0, 0);
    CP_COMMIT();
    load_stage(1, 1);
    CP_COMMIT();

    uint32_t ah[4][4];
    uint32_t bh[2][4];

    for (int t = 0; t < ntiles; t++) {
        float acc[4][8][4];
        #pragma unroll
        for (int i = 0; i < 4; i++)
            #pragma unroll
            for (int jj = 0; jj < 8; jj++)
                #pragma unroll
                for (int k = 0; k < 4; k++) acc[i][jj][k] = 0.f;

        for (int c = 0; c < NC; ++c) {
            CP_WAIT0();
            __syncthreads();

            const uint32_t bc = sb + (c % NSTAGE) * STAGE;
            const uint32_t bn = sb + ((c + 1) % NSTAGE) * STAGE;
            const bool hasnext = (c + 1 < NC);

            if (c == 0) {
                #pragma unroll
                for (int mf = 0; mf < 4; mf++)
                    LDM4(ah[mf], a_addr(bc, wm, lane, mf, 0));
                LDM4(bh[0], b_addr(bc, wn, lane, 0, 0));
            }

            if (c + 2 < NC) {
                load_stage((c + 2) % NSTAGE, c + 2);
                CP_COMMIT();
            }

            #pragma unroll
            for (int ks = 0; ks < 4; ks++) {
                #pragma unroll
                for (int ng = 0; ng < 4; ng++) {
                    const int tp = ((ks << 2) + ng) & 1;
                    if (!(ks == 3 && ng == 3)) {
                        const int nks = (ng == 3) ? ks + 1 : ks;
                        const int nng = (ng == 3) ? 0 : ng + 1;
                        LDM4(bh[tp ^ 1], b_addr(bc, wn, lane, nng, nks));
                    } else if (hasnext) {
                        LDM4(bh[0], b_addr(bn, wn, lane, 0, 0));
                    }
                    #pragma unroll
                    for (int mf = 0; mf < 4; mf++)
                        #pragma unroll
                        for (int h = 0; h < 2; h++)
                            MMAF16(acc[mf][(ng << 1) + h], ah[mf],
                                   bh[tp][2 * h], bh[tp][2 * h + 1]);
                    if (ng == 3) {
                        if (ks < 3) {
                            #pragma unroll
                            for (int mf = 0; mf < 4; mf++)
                                LDM4(ah[mf], a_addr(bc, wm, lane, mf, ks + 1));
                        } else if (hasnext) {
                            #pragma unroll
                            for (int mf = 0; mf < 4; mf++)
                                LDM4(ah[mf], a_addr(bn, wm, lane, mf, 0));
                        }
                    }
                }
            }
        }
        __syncthreads();   // mainloop done; smem stages free

        // Epilogue: y = coef * acc + bias
        #pragma unroll
        for (int mf = 0; mf < 4; mf++) {
            const int r = m0 + (wm << 6) + (mf << 4) + (lane >> 2);
            #pragma unroll
            for (int nf = 0; nf < 8; nf++) {
                const int cc = n0 + (wn << 6) + (nf << 3) + ((lane & 3) << 1);
                const float k0 = __ldg(&g_coef[cc]);
                const float k1 = __ldg(&g_coef[cc + 1]);
                const float b0 = __ldg(bias + cc);
                const float b1 = __ldg(bias + cc + 1);
                float2 v0 = { acc[mf][nf][0] * k0 + b0, acc[mf][nf][1] * k1 + b1 };
                float2 v1 = { acc[mf][nf][2] * k0 + b0, acc[mf][nf][3] * k1 + b1 };
                *(float2*)(y + (size_t)r * N_OUT + cc)       = v0;
                *(float2*)(y + (size_t)(r + 8) * N_OUT + cc) = v1;
            }
        }

        if (t + 1 < ntiles) {
            j = 591 - s;
            nt = 31 - (j >> 4);
            mt = j & 15;
            n0 = nt << 7;
            m0 = mt << 7;
            NC = (nt + 1) << 1;
            gA = g_xh + (size_t)m0 * K_IN;
            gB = g_wh + (size_t)n0 * K_IN;
            __syncthreads();   // stores issued; smem scratch safe for items
            gate_work(nt, mt, ep, W, wls, xin, jac, sred, s_stat);
            __threadfence();
            __syncthreads();
            load_stage(0, 0);
            CP_COMMIT();
            load_stage(1, 1);
            CP_COMMIT();
        }
    }
}

// ---------------------------------------------------------------------------
extern "C" void kernel_launch(void* const* d_in, const int* in_sizes, int n_in,
                              void* d_out, int out_size) {
    const float* x    = (const float*)d_in[0];
    const float* W    = (const float*)d_in[1];
    const float* bias = (const float*)d_in[2];
    const float* wls  = (const float*)d_in[3];
    // masks (d_in[4], d_in[5]) deterministic; never read.

    float* y   = (float*)d_out;
    float* jac = y + (size_t)M_BATCH * N_OUT;

    cudaFuncSetAttribute(fused, cudaFuncAttributeMaxDynamicSharedMemorySize,
                         SMEM_TOTAL);

    fused<<<NCTA, 128, SMEM_TOTAL>>>(x, W, wls, bias, y, jac);
}

// round 16
// speedup vs baseline: 1.1475x; 1.1475x over previous
#include <cuda_runtime.h>
#include <cuda_fp16.h>
#include <math.h>
#include <stdint.h>

#define M_BATCH 2048
#define N_OUT   4096
#define K_IN    4096
#define NPREP   6144            // 128 (Wgrp31) + 2048 (x rows) + 3968 (W desc)
#define NGEMM   296
#define NGRID   (NPREP + NGEMM)

// Persistent state (module-load allocations; no runtime alloc).
__device__ __half g_xh[(size_t)M_BATCH * K_IN];   // fp16(x)
__device__ __half g_wh[(size_t)N_OUT * K_IN];     // fp16(Wn) (scaled, padded)
__device__ unsigned g_entry;                      // monotonic epoch counter
__device__ unsigned g_wcnt[32];                   // per-W-128-group completion
__device__ unsigned g_xcnt[16];                   // per-x-128-group completion

// ---------------------------------------------------------------------------
__device__ __forceinline__ uint32_t smem_u32(const void* p) {
    uint32_t a;
    asm("{ .reg .u64 t; cvta.to.shared.u64 t, %1; cvt.u32.u64 %0, t; }"
        : "=r"(a) : "l"(p));
    return a;
}
__device__ __forceinline__ void cp16(uint32_t s, const void* g) {
    asm volatile("cp.async.cg.shared.global [%0], [%1], 16;" :: "r"(s), "l"(g));
}
#define CP_COMMIT() asm volatile("cp.async.commit_group;" ::: "memory")
#define CP_WAIT0()  asm volatile("cp.async.wait_group 0;" ::: "memory")

#define LDM4(d, addr)                                                         \
    asm volatile("ldmatrix.sync.aligned.m8n8.x4.shared.b16 {%0,%1,%2,%3}, [%4];" \
        : "=r"((d)[0]), "=r"((d)[1]), "=r"((d)[2]), "=r"((d)[3]) : "r"(addr))

#define MMAF16(c, a, b0, b1)                                                  \
    asm volatile("mma.sync.aligned.m16n8k16.row.col.f32.f16.f16.f32 "         \
        "{%0,%1,%2,%3}, {%4,%5,%6,%7}, {%8,%9}, {%0,%1,%2,%3};"               \
        : "+f"((c)[0]), "+f"((c)[1]), "+f"((c)[2]), "+f"((c)[3])              \
        : "r"((a)[0]), "r"((a)[1]), "r"((a)[2]), "r"((a)[3]), "r"(b0), "r"(b1))

__device__ __forceinline__ uint32_t pack2(float a, float b) {
    __half2 h = __halves2half2(__float2half_rn(a), __float2half_rn(b));
    return *(uint32_t*)&h;
}

// ---------------------------------------------------------------------------
// GEMM addressing (R14, verified)
// ---------------------------------------------------------------------------
#define STAGE 32768
#define NSTAGE 3
#define SMEM_TOTAL (NSTAGE * STAGE)

__device__ __forceinline__ uint32_t a_addr(uint32_t base, int wm, int lane,
                                           int mf, int ks) {
    const int row = (wm << 6) + (mf << 4) + (lane & 15);
    const int ch = ((ks << 1) + (lane >> 4)) ^ (row & 7);
    return base + (row << 7) + (ch << 4);
}
__device__ __forceinline__ uint32_t b_addr(uint32_t base, int wn, int lane,
                                           int ng, int ks) {
    const int n = (wn << 6) + (ng << 4) + ((lane >> 4) << 3) + (lane & 7);
    const int ch = ((ks << 1) + ((lane >> 3) & 1)) ^ (n & 7);
    return base + 16384 + (n << 7) + (ch << 4);
}

// Spin-gate (no stealing): producers are independently-progressing prep CTAs.
__device__ __forceinline__ void gate(int gw, int gx, unsigned wt) {
    if (threadIdx.x == 0) {
        while (atomicAdd(&g_wcnt[gw], 0u) < wt) __nanosleep(100);
        while (atomicAdd(&g_xcnt[gx], 0u) < wt) __nanosleep(100);
    }
    __threadfence();
    __syncthreads();
}

// ---------------------------------------------------------------------------
// Fused single-launch kernel. blockIdx < NPREP: prep CTA (one W or x row).
// blockIdx >= NPREP: persistent GEMM slot (R14 body + gates).
// In-order dispatch => all prep CTAs dispatched (and draining at full DRAM BW)
// before any GEMM CTA exists; GEMM CTAs fill slots as prep retires.
// Prep order: W group 31 first, then all x rows, then W rows descending —
// matching the heavy-tile-first GEMM consumption order.
// ---------------------------------------------------------------------------
__global__ __launch_bounds__(128, 2)
void fused(const float* __restrict__ xin, const float* __restrict__ W,
           const float* __restrict__ wls, const float* __restrict__ bias,
           float* __restrict__ y, float* __restrict__ jac) {
    extern __shared__ __align__(1024) char smem[];
    const int tid  = threadIdx.x;
    const int bid  = blockIdx.x;

    __shared__ unsigned s_ep;
    if (tid == 0) s_ep = atomicAdd(&g_entry, 1u) / NGRID;
    __syncthreads();
    const unsigned ep = s_ep;
    const unsigned tgt = (ep + 1u) * 128u;

    // ===================== Prep species ====================================
    if (bid < NPREP) {
        if (bid >= 128 && bid < 2176) {
            // ---- x row -> fp16 ----
            const int r = bid - 128;
            const size_t base = (size_t)r * K_IN;
            #pragma unroll
            for (int u = 0; u < 4; u++) {
                size_t i = base + (size_t)u * 1024 + tid * 8;
                float4 a = *(const float4*)(xin + i);
                float4 b = *(const float4*)(xin + i + 4);
                uint4 out = { pack2(a.x, a.y), pack2(a.z, a.w),
                              pack2(b.x, b.y), pack2(b.z, b.w) };
                *(uint4*)(&g_xh[i]) = out;
            }
            __threadfence();
            __syncthreads();
            if (tid == 0) atomicAdd(&g_xcnt[r >> 7], 1u);
        } else {
            // ---- W row: norm + scaled fp16 + jac + zero-pad ----
            const int o = (bid < 128) ? (4095 - bid) : (3967 - (bid - 2176));
            const int br = o >> 5, ncols = (br + 1) << 5, dstart = br << 5;
            const int kmax = ((o >> 7) + 1) << 7;
            float* row  = (float*)smem;            // 16 KB cache
            float* sred = (float*)(smem + 16384);

            const float* wrow = W + (size_t)o * K_IN;
            __half* wh = g_wh + (size_t)o * K_IN;

            float ss = 0.f;
            for (int base = tid * 8; base < ncols; base += 1024) {
                float4 a = *(const float4*)(wrow + base);
                float4 b = *(const float4*)(wrow + base + 4);
                *(float4*)(row + base)     = a;
                *(float4*)(row + base + 4) = b;
                float w[8] = { a.x, a.y, a.z, a.w, b.x, b.y, b.z, b.w };
                #pragma unroll
                for (int e = 0; e < 8; e++) {
                    float wm = (base + e >= dstart) ? expf(w[e]) : w[e];
                    ss += wm * wm;
                }
            }
            #pragma unroll
            for (int off = 16; off; off >>= 1)
                ss += __shfl_xor_sync(0xffffffffu, ss, off);
            if ((tid & 31) == 0) sred[tid >> 5] = ss;
            __syncthreads();
            if (tid == 0) {
                float s2 = sred[0] + sred[1] + sred[2] + sred[3];
                float norm = sqrtf(s2);
                float ls = wls[o];
                sred[4] = expf(ls) / norm;     // coef
                sred[5] = ls - logf(norm);     // jac offset
            }
            __syncthreads();
            const float coef = sred[4];
            const float joff = sred[5];

            for (int base = tid * 8; base < ncols; base += 1024) {
                float wn[8];
                #pragma unroll
                for (int e = 0; e < 8; e++) {
                    float w = row[base + e];
                    float wm = (base + e >= dstart) ? expf(w) : w;
                    wn[e] = coef * wm;
                }
                uint4 out = { pack2(wn[0], wn[1]), pack2(wn[2], wn[3]),
                              pack2(wn[4], wn[5]), pack2(wn[6], wn[7]) };
                *(uint4*)(wh + base) = out;
            }
            const uint4 z4 = {0u, 0u, 0u, 0u};
            for (int base = ncols + tid * 8; base < kmax; base += 1024)
                *(uint4*)(wh + base) = z4;
            if (tid < 32)
                jac[(size_t)o * 32 + tid] = joff + row[dstart + tid];
            __threadfence();
            __syncthreads();
            if (tid == 0) atomicAdd(&g_wcnt[o >> 7], 1u);
        }
        return;
    }

    // ===================== GEMM species (R14 body + gates) =================
    const uint32_t sb = smem_u32(smem);
    const int wid  = tid >> 5;
    const int lane = tid & 31;
    const int wm = wid >> 1;
    const int wn = wid & 1;

    const int s = bid - NPREP;           // slot 0..295
    const int ntiles = (s >= 80) ? 2 : 1;

    int j = s;
    int nt = 31 - (j >> 4);
    int mt = j & 15;
    int n0 = nt << 7;
    int m0 = mt << 7;
    int NC = (nt + 1) << 1;

    const __half* gA = g_xh + (size_t)m0 * K_IN;
    const __half* gB = g_wh + (size_t)n0 * K_IN;

    auto load_stage = [&](int st, int c) {
        const uint32_t base = sb + st * STAGE;
        const int k0 = c << 6;
        #pragma unroll
        for (int i = 0; i < 8; i++) {
            const int idx = tid + (i << 7);
            const int r = idx >> 3;
            const int ch = idx & 7;
            const size_t go = (size_t)r * K_IN + k0 + (ch << 3);
            const uint32_t so = (uint32_t)((r << 7) | ((ch ^ (r & 7)) << 4));
            cp16(base + so,         gA + go);
            cp16(base + 16384 + so, gB + go);
        }
    };

    gate(nt, mt, tgt);
    load_stage(0, 0);
    CP_COMMIT();
    load_stage(1, 1);
    CP_COMMIT();

    uint32_t ah[4][4];
    uint32_t bh[2][4];

    for (int t = 0; t < ntiles; t++) {
        float acc[4][8][4];
        #pragma unroll
        for (int i = 0; i < 4; i++)
            #pragma unroll
            for (int jj = 0; jj < 8; jj++)
                #pragma unroll
                for (int k = 0; k < 4; k++) acc[i][jj][k] = 0.f;

        for (int c = 0; c < NC; ++c) {
            CP_WAIT0();
            __syncthreads();

            const uint32_t bc = sb + (c % NSTAGE) * STAGE;
            const uint32_t bn = sb + ((c + 1) % NSTAGE) * STAGE;
            const bool hasnext = (c + 1 < NC);

            if (c == 0) {
                #pragma unroll
                for (int mf = 0; mf < 4; mf++)
                    LDM4(ah[mf], a_addr(bc, wm, lane, mf, 0));
                LDM4(bh[0], b_addr(bc, wn, lane, 0, 0));
            }

            if (c + 2 < NC) {
                load_stage((c + 2) % NSTAGE, c + 2);
                CP_COMMIT();
            }

            #pragma unroll
            for (int ks = 0; ks < 4; ks++) {
                #pragma unroll
                for (int ng = 0; ng < 4; ng++) {
                    const int tp = ((ks << 2) + ng) & 1;
                    if (!(ks == 3 && ng == 3)) {
                        const int nks = (ng == 3) ? ks + 1 : ks;
                        const int nng = (ng == 3) ? 0 : ng + 1;
                        LDM4(bh[tp ^ 1], b_addr(bc, wn, lane, nng, nks));
                    } else if (hasnext) {
                        LDM4(bh[0], b_addr(bn, wn, lane, 0, 0));
                    }
                    #pragma unroll
                    for (int mf = 0; mf < 4; mf++)
                        #pragma unroll
                        for (int h = 0; h < 2; h++)
                            MMAF16(acc[mf][(ng << 1) + h], ah[mf],
                                   bh[tp][2 * h], bh[tp][2 * h + 1]);
                    if (ng == 3) {
                        if (ks < 3) {
                            #pragma unroll
                            for (int mf = 0; mf < 4; mf++)
                                LDM4(ah[mf], a_addr(bc, wm, lane, mf, ks + 1));
                        } else if (hasnext) {
                            #pragma unroll
                            for (int mf = 0; mf < 4; mf++)
                                LDM4(ah[mf], a_addr(bn, wm, lane, mf, 0));
                        }
                    }
                }
            }
        }

        const int m0_out = m0, n0_out = n0;

        __syncthreads();
        if (t + 1 < ntiles) {
            j = 591 - s;
            nt = 31 - (j >> 4);
            mt = j & 15;
            n0 = nt << 7;
            m0 = mt << 7;
            NC = (nt + 1) << 1;
            gA = g_xh + (size_t)m0 * K_IN;
            gB = g_wh + (size_t)n0 * K_IN;
            gate(nt, mt, tgt);           // light/late tiles: almost always open
            load_stage(0, 0);
            CP_COMMIT();
            load_stage(1, 1);
            CP_COMMIT();
        }

        #pragma unroll
        for (int mf = 0; mf < 4; mf++) {
            const int r = m0_out + (wm << 6) + (mf << 4) + (lane >> 2);
            #pragma unroll
            for (int nf = 0; nf < 8; nf++) {
                const int cc = n0_out + (wn << 6) + (nf << 3) + ((lane & 3) << 1);
                const float b0 = __ldg(bias + cc);
                const float b1 = __ldg(bias + cc + 1);
                float2 v0 = { acc[mf][nf][0] + b0, acc[mf][nf][1] + b1 };
                float2 v1 = { acc[mf][nf][2] + b0, acc[mf][nf][3] + b1 };
                *(float2*)(y + (size_t)r * N_OUT + cc)       = v0;
                *(float2*)(y + (size_t)(r + 8) * N_OUT + cc) = v1;
            }
        }
    }
}

// ---------------------------------------------------------------------------
extern "C" void kernel_launch(void* const* d_in, const int* in_sizes, int n_in,
                              void* d_out, int out_size) {
    const float* x    = (const float*)d_in[0];
    const float* W    = (const float*)d_in[1];
    const float* bias = (const float*)d_in[2];
    const float* wls  = (const float*)d_in[3];
    // masks (d_in[4], d_in[5]) deterministic; never read.

    float* y   = (float*)d_out;
    float* jac = y + (size_t)M_BATCH * N_OUT;

    cudaFuncSetAttribute(fused, cudaFuncAttributeMaxDynamicSharedMemorySize,
                         SMEM_TOTAL);

    fused<<<NGRID, 128, SMEM_TOTAL>>>(x, W, wls, bias, y, jac);
}

// round 17
// speedup vs baseline: 1.5856x; 1.3817x over previous
#include <cuda_runtime.h>
#include <cuda_fp16.h>
#include <math.h>
#include <stdint.h>

#define M_BATCH 2048
#define N_OUT   4096
#define K_IN    4096
#define NGEMM   296

// Persistent state (module-load allocations; no runtime alloc).
__device__ __half g_xh[(size_t)M_BATCH * K_IN];   // fp16(x)
__device__ __half g_wh[(size_t)N_OUT * K_IN];     // fp16(Wn)
__device__ unsigned g_entry;                      // monotonic epoch counter
__device__ unsigned g_sflag[64];                  // split-tile h0-done flags

// ---------------------------------------------------------------------------
__device__ __forceinline__ uint32_t smem_u32(const void* p) {
    uint32_t a;
    asm("{ .reg .u64 t; cvta.to.shared.u64 t, %1; cvt.u32.u64 %0, t; }"
        : "=r"(a) : "l"(p));
    return a;
}
__device__ __forceinline__ void cp16(uint32_t s, const void* g) {
    asm volatile("cp.async.cg.shared.global [%0], [%1], 16;" :: "r"(s), "l"(g));
}
#define CP_COMMIT() asm volatile("cp.async.commit_group;" ::: "memory")
#define CP_WAIT0()  asm volatile("cp.async.wait_group 0;" ::: "memory")

#define LDM4(d, addr)                                                         \
    asm volatile("ldmatrix.sync.aligned.m8n8.x4.shared.b16 {%0,%1,%2,%3}, [%4];" \
        : "=r"((d)[0]), "=r"((d)[1]), "=r"((d)[2]), "=r"((d)[3]) : "r"(addr))

#define MMAF16(c, a, b0, b1)                                                  \
    asm volatile("mma.sync.aligned.m16n8k16.row.col.f32.f16.f16.f32 "         \
        "{%0,%1,%2,%3}, {%4,%5,%6,%7}, {%8,%9}, {%0,%1,%2,%3};"               \
        : "+f"((c)[0]), "+f"((c)[1]), "+f"((c)[2]), "+f"((c)[3])              \
        : "r"((a)[0]), "r"((a)[1]), "r"((a)[2]), "r"((a)[3]), "r"(b0), "r"(b1))

__device__ __forceinline__ uint32_t pack2(float a, float b) {
    __half2 h = __halves2half2(__float2half_rn(a), __float2half_rn(b));
    return *(uint32_t*)&h;
}

// ---------------------------------------------------------------------------
// Merged prep (R12/R14, proven): blocks [0,4096) W rows; [4096,8192) x slices.
// ---------------------------------------------------------------------------
__global__ void prep_all(const float* __restrict__ x,
                         const float* __restrict__ W,
                         const float* __restrict__ wls,
                         float* __restrict__ jac_out) {
    extern __shared__ float sh[];    // [4096] row cache + [256] reduction
    const int tid = threadIdx.x;
    if (blockIdx.x < 4096) {
        const int o = blockIdx.x;
        const int br = o >> 5;
        const int ncols = (br + 1) << 5;
        const int dstart = br << 5;
        const int kmax_tile = ((o >> 7) + 1) << 7;

        float* row = sh;
        float* red = sh + 4096;

        const float* wrow = W + (size_t)o * K_IN;
        __half* wh = g_wh + (size_t)o * K_IN;

        float ss = 0.f;
        for (int base = tid * 8; base < ncols; base += 2048) {
            float4 a = *(const float4*)(wrow + base);
            float4 b = *(const float4*)(wrow + base + 4);
            *(float4*)(row + base)     = a;
            *(float4*)(row + base + 4) = b;
            float w[8] = { a.x, a.y, a.z, a.w, b.x, b.y, b.z, b.w };
            #pragma unroll
            for (int e = 0; e < 8; e++) {
                float wm = (base + e >= dstart) ? expf(w[e]) : w[e];
                ss += wm * wm;
            }
        }
        red[tid] = ss;
        __syncthreads();
        #pragma unroll
        for (int s = 128; s > 0; s >>= 1) {
            if (tid < s) red[tid] += red[tid + s];
            __syncthreads();
        }
        const float norm   = sqrtf(red[0]);
        const float lscale = wls[o];
        const float coef   = expf(lscale) / norm;
        const float logn   = logf(norm);

        for (int base = tid * 8; base < ncols; base += 2048) {
            float wn[8];
            #pragma unroll
            for (int e = 0; e < 8; e++) {
                float w = row[base + e];
                float wm = (base + e >= dstart) ? expf(w) : w;
                wn[e] = coef * wm;
                if (base + e >= dstart)
                    jac_out[(size_t)o * 32 + (base + e - dstart)] =
                        lscale + w - logn;
            }
            uint4 out = { pack2(wn[0], wn[1]), pack2(wn[2], wn[3]),
                          pack2(wn[4], wn[5]), pack2(wn[6], wn[7]) };
            *(uint4*)(wh + base) = out;
        }
        const uint4 z4 = {0u, 0u, 0u, 0u};
        for (int base = ncols + tid * 8; base < kmax_tile; base += 2048)
            *(uint4*)(wh + base) = z4;
    } else {
        size_t i = ((size_t)(blockIdx.x - 4096) * blockDim.x + tid) * 8;
        float4 a = *(const float4*)(x + i);
        float4 b = *(const float4*)(x + i + 4);
        uint4 out = { pack2(a.x, a.y), pack2(a.z, a.w),
                      pack2(b.x, b.y), pack2(b.z, b.w) };
        *(uint4*)(&g_xh[i]) = out;
    }
}

// ---------------------------------------------------------------------------
// Unit decode: 576 work units = 448 whole tiles (j>=64) + 128 halves of the
// 64 heaviest tiles (j<64, NC 58..64 -> two NC/2 halves). Units are listed in
// descending cost order; slot s runs unit s, then unit 575-s if s<280.
// kind: 0 = whole, 1 = half0 (writes y+bias, sets flag), 2 = half1 (REDG add).
// ---------------------------------------------------------------------------
__device__ __forceinline__ void decode_unit(int u, int& j, int& cb,
                                            int& cnt, int& kind) {
    const int grp = u >> 4, k = u & 15;
    int jj, h = -1;
    if (grp < 12)       jj = 64 + (grp << 4) + k;        // NC 56..34
    else if (grp == 12) { jj = k;       h = 0; }         // c32
    else if (grp == 13) { jj = k;       h = 1; }
    else if (grp == 14) jj = 256 + k;                    // NC 32
    else if (grp == 15) { jj = 16 + k;  h = 0; }         // c31
    else if (grp == 16) { jj = 16 + k;  h = 1; }
    else if (grp == 17) { jj = 32 + k;  h = 0; }         // c30
    else if (grp == 18) { jj = 32 + k;  h = 1; }
    else if (grp == 19) jj = 272 + k;                    // NC 30
    else if (grp == 20) { jj = 48 + k;  h = 0; }         // c29
    else if (grp == 21) { jj = 48 + k;  h = 1; }
    else                jj = 288 + ((grp - 22) << 4) + k; // NC 28..2
    const int NC = 64 - 2 * (jj >> 4);
    if (h < 0) { cb = 0; cnt = NC; kind = 0; }
    else { const int nh = NC >> 1; cb = h * nh; cnt = nh; kind = 1 + h; }
    j = jj;
}

// ---------------------------------------------------------------------------
// Persistent fp16 GEMM (R14 mainloop) over the split-K unit schedule.
// 296 CTAs (2/SM), 128 threads (2m x 2n warps => 64x64), CTA tile 128x128,
// BK=64, 3-stage cp.async, register-pipelined fragments.
// ---------------------------------------------------------------------------
#define STAGE 32768
#define NSTAGE 3
#define SMEM_TOTAL (NSTAGE * STAGE)

__device__ __forceinline__ uint32_t a_addr(uint32_t base, int wm, int lane,
                                           int mf, int ks) {
    const int row = (wm << 6) + (mf << 4) + (lane & 15);
    const int ch = ((ks << 1) + (lane >> 4)) ^ (row & 7);
    return base + (row << 7) + (ch << 4);
}
__device__ __forceinline__ uint32_t b_addr(uint32_t base, int wn, int lane,
                                           int ng, int ks) {
    const int n = (wn << 6) + (ng << 4) + ((lane >> 4) << 3) + (lane & 7);
    const int ch = ((ks << 1) + ((lane >> 3) & 1)) ^ (n & 7);
    return base + 16384 + (n << 7) + (ch << 4);
}

__global__ __launch_bounds__(128, 2)
void gemm_mma(const float* __restrict__ bias, float* __restrict__ y) {
    extern __shared__ __align__(1024) char smem[];
    const uint32_t sb = smem_u32(smem);

    const int tid  = threadIdx.x;
    const int wid  = tid >> 5;
    const int lane = tid & 31;
    const int wm = wid >> 1;
    const int wn = wid & 1;

    __shared__ unsigned s_ep;
    if (tid == 0) s_ep = atomicAdd(&g_entry, 1u) / (unsigned)NGEMM;
    __syncthreads();
    const unsigned ftgt = s_ep + 1u;

    const int s = blockIdx.x;
    const int nunits = (s < 280) ? 2 : 1;

    int j, cb, cnt, kind;
    decode_unit(s, j, cb, cnt, kind);
    int nt = 31 - (j >> 4), mt = j & 15;
    int n0 = nt << 7, m0 = mt << 7;

    const __half* gA = g_xh + (size_t)m0 * K_IN;
    const __half* gB = g_wh + (size_t)n0 * K_IN;

    auto load_stage = [&](int st, int ca) {      // ca = absolute chunk index
        const uint32_t base = sb + st * STAGE;
        const int k0 = ca << 6;
        #pragma unroll
        for (int i = 0; i < 8; i++) {
            const int idx = tid + (i << 7);
            const int r = idx >> 3;
            const int ch = idx & 7;
            const size_t go = (size_t)r * K_IN + k0 + (ch << 3);
            const uint32_t so = (uint32_t)((r << 7) | ((ch ^ (r & 7)) << 4));
            cp16(base + so,         gA + go);
            cp16(base + 16384 + so, gB + go);
        }
    };

    // Prologue for unit 0 (cnt >= 2 always).
    load_stage(0, cb);
    CP_COMMIT();
    load_stage(1, cb + 1);
    CP_COMMIT();

    uint32_t ah[4][4];
    uint32_t bh[2][4];

    for (int t = 0; t < nunits; t++) {
        float acc[4][8][4];
        #pragma unroll
        for (int i = 0; i < 4; i++)
            #pragma unroll
            for (int jj = 0; jj < 8; jj++)
                #pragma unroll
                for (int k = 0; k < 4; k++) acc[i][jj][k] = 0.f;

        for (int c = 0; c < cnt; ++c) {
            CP_WAIT0();
            __syncthreads();

            const uint32_t bc = sb + (c % NSTAGE) * STAGE;
            const uint32_t bn = sb + ((c + 1) % NSTAGE) * STAGE;
            const bool hasnext = (c + 1 < cnt);

            if (c == 0) {
                #pragma unroll
                for (int mf = 0; mf < 4; mf++)
                    LDM4(ah[mf], a_addr(bc, wm, lane, mf, 0));
                LDM4(bh[0], b_addr(bc, wn, lane, 0, 0));
            }

            if (c + 2 < cnt) {
                load_stage((c + 2) % NSTAGE, cb + c + 2);
                CP_COMMIT();
            }

            #pragma unroll
            for (int ks = 0; ks < 4; ks++) {
                #pragma unroll
                for (int ng = 0; ng < 4; ng++) {
                    const int tp = ((ks << 2) + ng) & 1;
                    if (!(ks == 3 && ng == 3)) {
                        const int nks = (ng == 3) ? ks + 1 : ks;
                        const int nng = (ng == 3) ? 0 : ng + 1;
                        LDM4(bh[tp ^ 1], b_addr(bc, wn, lane, nng, nks));
                    } else if (hasnext) {
                        LDM4(bh[0], b_addr(bn, wn, lane, 0, 0));
                    }
                    #pragma unroll
                    for (int mf = 0; mf < 4; mf++)
                        #pragma unroll
                        for (int h = 0; h < 2; h++)
                            MMAF16(acc[mf][(ng << 1) + h], ah[mf],
                                   bh[tp][2 * h], bh[tp][2 * h + 1]);
                    if (ng == 3) {
                        if (ks < 3) {
                            #pragma unroll
                            for (int mf = 0; mf < 4; mf++)
                                LDM4(ah[mf], a_addr(bc, wm, lane, mf, ks + 1));
                        } else if (hasnext) {
                            #pragma unroll
                            for (int mf = 0; mf < 4; mf++)
                                LDM4(ah[mf], a_addr(bn, wm, lane, mf, 0));
                        }
                    }
                }
            }
        }

        const int m0_out = m0, n0_out = n0, j_out = j, kind_out = kind;

        __syncthreads();   // all warps done with this unit's smem
        if (t + 1 < nunits) {
            decode_unit(575 - s, j, cb, cnt, kind);
            nt = 31 - (j >> 4);
            mt = j & 15;
            n0 = nt << 7;
            m0 = mt << 7;
            gA = g_xh + (size_t)m0 * K_IN;
            gB = g_wh + (size_t)n0 * K_IN;
            load_stage(0, cb);        // next unit's prologue hides under epilogue
            CP_COMMIT();
            load_stage(1, cb + 1);
            CP_COMMIT();
        }

        // Epilogue for the finished unit.
        if (kind_out == 2) {
            // half1: wait for half0's write (flag-ordered), then add partials.
            if (tid == 0) {
                while (atomicAdd(&g_sflag[j_out], 0u) < ftgt) __nanosleep(100);
            }
            __syncthreads();
            __threadfence();
            #pragma unroll
            for (int mf = 0; mf < 4; mf++) {
                const int r = m0_out + (wm << 6) + (mf << 4) + (lane >> 2);
                #pragma unroll
                for (int nf = 0; nf < 8; nf++) {
                    const int cc = n0_out + (wn << 6) + (nf << 3) + ((lane & 3) << 1);
                    float* p0 = y + (size_t)r * N_OUT + cc;
                    float* p1 = y + (size_t)(r + 8) * N_OUT + cc;
                    atomicAdd(p0,     acc[mf][nf][0]);
                    atomicAdd(p0 + 1, acc[mf][nf][1]);
                    atomicAdd(p1,     acc[mf][nf][2]);
                    atomicAdd(p1 + 1, acc[mf][nf][3]);
                }
            }
        } else {
            #pragma unroll
            for (int mf = 0; mf < 4; mf++) {
                const int r = m0_out + (wm << 6) + (mf << 4) + (lane >> 2);
                #pragma unroll
                for (int nf = 0; nf < 8; nf++) {
                    const int cc = n0_out + (wn << 6) + (nf << 3) + ((lane & 3) << 1);
                    const float b0 = __ldg(bias + cc);
                    const float b1 = __ldg(bias + cc + 1);
                    float2 v0 = { acc[mf][nf][0] + b0, acc[mf][nf][1] + b1 };
                    float2 v1 = { acc[mf][nf][2] + b0, acc[mf][nf][3] + b1 };
                    *(float2*)(y + (size_t)r * N_OUT + cc)       = v0;
                    *(float2*)(y + (size_t)(r + 8) * N_OUT + cc) = v1;
                }
            }
            if (kind_out == 1) {
                __threadfence();
                __syncthreads();
                if (tid == 0) atomicAdd(&g_sflag[j_out], 1u);
            }
        }
    }
}

// ---------------------------------------------------------------------------
extern "C" void kernel_launch(void* const* d_in, const int* in_sizes, int n_in,
                              void* d_out, int out_size) {
    const float* x    = (const float*)d_in[0];
    const float* W    = (const float*)d_in[1];
    const float* bias = (const float*)d_in[2];
    const float* wls  = (const float*)d_in[3];
    // masks (d_in[4], d_in[5]) deterministic; never read.

    float* y   = (float*)d_out;
    float* jac = y + (size_t)M_BATCH * N_OUT;

    cudaFuncSetAttribute(gemm_mma, cudaFuncAttributeMaxDynamicSharedMemorySize,
                         SMEM_TOTAL);

    prep_all<<<8192, 256, (4096 + 256) * sizeof(float)>>>(x, W, wls, jac);
    gemm_mma<<<NGEMM, 128, SMEM_TOTAL>>>(bias, y);
}